// round 1
// baseline (speedup 1.0000x reference)
#include <cuda_runtime.h>
#include <math.h>

// Problem constants (fixed by setup_inputs)
#define Bv    8
#define Tv    512
#define Cv    512
#define Hv    8
#define DHv   64
#define Lv    2
#define Vv    512
#define FFv   2048
#define STEPS 4
#define MALL  (Bv*Tv)          // 4096 rows
#define SCALE 0.125f           // 1/sqrt(64)

// ---------------- scratch (device globals; no allocation) ----------------
__device__ float g_x [MALL*Cv];
__device__ float g_xn[MALL*Cv];
__device__ float g_q [MALL*Cv];
__device__ float g_k [MALL*Cv];
__device__ float g_v [MALL*Cv];
__device__ float g_y [MALL*Cv];
__device__ float g_att[Bv*Hv*Tv*Tv];   // 16.7M floats
__device__ float g_h [MALL*FFv];

// ---------------- embedding ----------------
__global__ void embed_k(const int* __restrict__ idx,
                        const float* __restrict__ tok,
                        const float* __restrict__ pos,
                        float* __restrict__ x)
{
    int i = blockIdx.x * 256 + threadIdx.x;     // 0 .. MALL*Cv-1
    int c  = i & (Cv - 1);
    int bt = i >> 9;                            // Cv = 512
    int t  = bt & (Tv - 1);
    x[i] = tok[idx[bt] * Cv + c] + pos[t * Cv + c];
}

// ---------------- layernorm (one block per row, 256 thr, 2 elems each) ----------------
__device__ __forceinline__ float block_sum(float v, float* red)
{
    // warp reduce
    for (int o = 16; o > 0; o >>= 1) v += __shfl_xor_sync(0xffffffffu, v, o);
    int warp = threadIdx.x >> 5, lane = threadIdx.x & 31;
    if (lane == 0) red[warp] = v;
    __syncthreads();
    if (warp == 0) {
        float s = (lane < 8) ? red[lane] : 0.f;
        for (int o = 4; o > 0; o >>= 1) s += __shfl_xor_sync(0xffffffffu, s, o);
        if (lane == 0) red[0] = s;
    }
    __syncthreads();
    float r = red[0];
    __syncthreads();
    return r;
}

__global__ __launch_bounds__(256) void ln_k(const float* __restrict__ x,
                                            const float* __restrict__ g,
                                            const float* __restrict__ b,
                                            float* __restrict__ o)
{
    __shared__ float red[32];
    long row = blockIdx.x;
    const float* xr = x + row * Cv;
    int c0 = threadIdx.x, c1 = threadIdx.x + 256;
    float v0 = xr[c0], v1 = xr[c1];
    float mu = block_sum(v0 + v1, red) * (1.f / Cv);
    float d0 = v0 - mu, d1 = v1 - mu;
    float var = block_sum(d0 * d0 + d1 * d1, red) * (1.f / Cv);
    float inv = rsqrtf(var + 1e-5f);
    float* orow = o + row * Cv;
    orow[c0] = d0 * inv * g[c0] + b[c0];
    orow[c1] = d1 * inv * g[c1] + b[c1];
}

// ---------------- softmax over last dim (rows of 512) ----------------
__global__ __launch_bounds__(256) void softmax_k(float* __restrict__ a)
{
    __shared__ float red[32];
    long row = blockIdx.x;
    float* ar = a + row * Tv;
    int c0 = threadIdx.x, c1 = threadIdx.x + 256;
    float v0 = ar[c0], v1 = ar[c1];
    // max reduce
    float m = fmaxf(v0, v1);
    for (int o = 16; o > 0; o >>= 1) m = fmaxf(m, __shfl_xor_sync(0xffffffffu, m, o));
    int warp = threadIdx.x >> 5, lane = threadIdx.x & 31;
    if (lane == 0) red[warp] = m;
    __syncthreads();
    if (warp == 0) {
        float s = (lane < 8) ? red[lane] : -1e30f;
        for (int o = 4; o > 0; o >>= 1) s = fmaxf(s, __shfl_xor_sync(0xffffffffu, s, o));
        if (lane == 0) red[0] = s;
    }
    __syncthreads();
    m = red[0];
    __syncthreads();
    float e0 = expf(v0 - m), e1 = expf(v1 - m);
    float s = block_sum(e0 + e1, red);
    float inv = 1.f / s;
    ar[c0] = e0 * inv;
    ar[c1] = e1 * inv;
}

// ---------------- generic tiled GEMM ----------------
// C[m,n] = act( scale * sum_k A[m,k] * B'[k,n] + bias[n] + res[m,n] )
// B'[k,n] = TRANSB ? B[n*ldb+k] : B[k*ldb+n]
// batch: z -> (z1=z>>3, z2=z&7), pointer offsets z1*s?1 + z2*s?2
// All of M,N divisible by 64; K divisible by 16.
template <bool TRANSB, bool GELU_ACT>
__global__ __launch_bounds__(256) void gemm_k(
    const float* __restrict__ A, int lda, long long sA1, long long sA2,
    const float* __restrict__ Bm, int ldb, long long sB1, long long sB2,
    const float* __restrict__ bias,
    const float* __restrict__ res,
    float* __restrict__ Cm, int ldc, long long sC1, long long sC2,
    int K, float scale)
{
    int z = blockIdx.z;
    int z1 = z >> 3, z2 = z & 7;
    A  += z1 * sA1 + z2 * sA2;
    Bm += z1 * sB1 + z2 * sB2;
    Cm += z1 * sC1 + z2 * sC2;

    __shared__ float As[16][65];
    __shared__ float Bs[16][65];

    int tid = threadIdx.x;
    int tx = tid & 15, ty = tid >> 4;
    int rowBase = blockIdx.y * 64;
    int colBase = blockIdx.x * 64;

    float acc[4][4] = {};

    for (int k0 = 0; k0 < K; k0 += 16) {
        // load A tile 64(m) x 16(k): contiguous along k
#pragma unroll
        for (int i = 0; i < 4; i++) {
            int idx = tid + i * 256;
            int m = idx >> 4, kk = idx & 15;
            As[kk][m] = A[(long)(rowBase + m) * lda + (k0 + kk)];
        }
        // load B tile 16(k) x 64(n)
#pragma unroll
        for (int i = 0; i < 4; i++) {
            int idx = tid + i * 256;
            if (TRANSB) {
                int n = idx >> 4, kk = idx & 15;     // contiguous along k in gmem
                Bs[kk][n] = Bm[(long)(colBase + n) * ldb + (k0 + kk)];
            } else {
                int kk = idx >> 6, n = idx & 63;     // contiguous along n in gmem
                Bs[kk][n] = Bm[(long)(k0 + kk) * ldb + (colBase + n)];
            }
        }
        __syncthreads();
#pragma unroll
        for (int kk = 0; kk < 16; kk++) {
            float a[4], b[4];
#pragma unroll
            for (int i = 0; i < 4; i++) a[i] = As[kk][ty * 4 + i];
#pragma unroll
            for (int j = 0; j < 4; j++) b[j] = Bs[kk][tx * 4 + j];
#pragma unroll
            for (int i = 0; i < 4; i++)
#pragma unroll
                for (int j = 0; j < 4; j++)
                    acc[i][j] += a[i] * b[j];
        }
        __syncthreads();
    }

    // epilogue
#pragma unroll
    for (int i = 0; i < 4; i++) {
        int m = rowBase + ty * 4 + i;
#pragma unroll
        for (int j = 0; j < 4; j++) {
            int n = colBase + tx * 4 + j;
            float v = acc[i][j] * scale;
            if (bias) v += bias[n];
            if (res)  v += res[(long)m * ldc + n];
            if (GELU_ACT) v = 0.5f * v * (1.f + erff(v * 0.70710678118654752f));
            Cm[(long)m * ldc + n] = v;
        }
    }
}

// ---------------- host orchestration ----------------
extern "C" void kernel_launch(void* const* d_in, const int* in_sizes, int n_in,
                              void* d_out, int out_size)
{
    const int*   idx   = (const int*)  d_in[0];
    const float* tok   = (const float*)d_in[1];
    const float* pos   = (const float*)d_in[2];
    const float* ln1g  = (const float*)d_in[3];
    const float* ln1b  = (const float*)d_in[4];
    const float* Wq    = (const float*)d_in[5];
    const float* bq    = (const float*)d_in[6];
    const float* Wk    = (const float*)d_in[7];
    const float* bk    = (const float*)d_in[8];
    const float* Wv    = (const float*)d_in[9];
    const float* bv    = (const float*)d_in[10];
    const float* Wp    = (const float*)d_in[11];
    const float* bp    = (const float*)d_in[12];
    const float* ln2g  = (const float*)d_in[13];
    const float* ln2b  = (const float*)d_in[14];
    const float* W1    = (const float*)d_in[15];
    const float* b1    = (const float*)d_in[16];
    const float* W2    = (const float*)d_in[17];
    const float* b2    = (const float*)d_in[18];
    const float* lnfg  = (const float*)d_in[19];
    const float* lnfb  = (const float*)d_in[20];
    const float* Whead = (const float*)d_in[21];
    float* out = (float*)d_out;

    float *x, *xn, *q, *k, *v, *y, *att, *h;
    cudaGetSymbolAddress((void**)&x,   g_x);
    cudaGetSymbolAddress((void**)&xn,  g_xn);
    cudaGetSymbolAddress((void**)&q,   g_q);
    cudaGetSymbolAddress((void**)&k,   g_k);
    cudaGetSymbolAddress((void**)&v,   g_v);
    cudaGetSymbolAddress((void**)&y,   g_y);
    cudaGetSymbolAddress((void**)&att, g_att);
    cudaGetSymbolAddress((void**)&h,   g_h);

    const long long sTC  = (long long)Tv * Cv;      // per-batch stride in Q/K/V/Y
    const long long sHTT = (long long)Hv * Tv * Tv; // per-batch stride in att
    const long long sTT  = (long long)Tv * Tv;      // per-head stride in att

    // x = tok_emb[idx] + pos_emb
    embed_k<<<(MALL * Cv) / 256, 256>>>(idx, tok, pos, x);

    for (int s = 0; s < STEPS; s++) {
        for (int l = 0; l < Lv; l++) {
            const float* wq = Wq + (long)l * Cv * Cv;
            const float* wk = Wk + (long)l * Cv * Cv;
            const float* wv = Wv + (long)l * Cv * Cv;
            const float* wp = Wp + (long)l * Cv * Cv;
            const float* w1 = W1 + (long)l * Cv * FFv;
            const float* w2 = W2 + (long)l * FFv * Cv;

            // xn = LN1(x)
            ln_k<<<MALL, 256>>>(x, ln1g + l * Cv, ln1b + l * Cv, xn);

            // q/k/v = xn @ W + b
            dim3 gProj(Cv / 64, MALL / 64, 1);
            gemm_k<false, false><<<gProj, 256>>>(xn, Cv, 0, 0, wq, Cv, 0, 0,
                                                 bq + l * Cv, nullptr,
                                                 q, Cv, 0, 0, Cv, 1.f);
            gemm_k<false, false><<<gProj, 256>>>(xn, Cv, 0, 0, wk, Cv, 0, 0,
                                                 bk + l * Cv, nullptr,
                                                 k, Cv, 0, 0, Cv, 1.f);
            gemm_k<false, false><<<gProj, 256>>>(xn, Cv, 0, 0, wv, Cv, 0, 0,
                                                 bv + l * Cv, nullptr,
                                                 v, Cv, 0, 0, Cv, 1.f);

            // att = SCALE * q @ k^T   (batched over b,h)
            dim3 gQK(Tv / 64, Tv / 64, Bv * Hv);
            gemm_k<true, false><<<gQK, 256>>>(q, Cv, sTC, DHv,
                                              k, Cv, sTC, DHv,
                                              nullptr, nullptr,
                                              att, Tv, sHTT, sTT,
                                              DHv, SCALE);

            // softmax along k
            softmax_k<<<Bv * Hv * Tv, 256>>>(att);

            // y = att @ v   (batched over b,h; N = 64)
            dim3 gAV(DHv / 64, Tv / 64, Bv * Hv);
            gemm_k<false, false><<<gAV, 256>>>(att, Tv, sHTT, sTT,
                                               v, Cv, sTC, DHv,
                                               nullptr, nullptr,
                                               y, Cv, sTC, DHv,
                                               Tv, 1.f);

            // x = x + y @ Wp + bp
            gemm_k<false, false><<<gProj, 256>>>(y, Cv, 0, 0, wp, Cv, 0, 0,
                                                 bp + l * Cv, x,
                                                 x, Cv, 0, 0, Cv, 1.f);

            // xn = LN2(x)
            ln_k<<<MALL, 256>>>(x, ln2g + l * Cv, ln2b + l * Cv, xn);

            // h = gelu(xn @ W1 + b1)
            dim3 gFF1(FFv / 64, MALL / 64, 1);
            gemm_k<false, true><<<gFF1, 256>>>(xn, Cv, 0, 0, w1, FFv, 0, 0,
                                               b1 + l * FFv, nullptr,
                                               h, FFv, 0, 0, Cv, 1.f);

            // x = x + h @ W2 + b2
            gemm_k<false, false><<<gProj, 256>>>(h, FFv, 0, 0, w2, Cv, 0, 0,
                                                 b2 + l * Cv, x,
                                                 x, Cv, 0, 0, FFv, 1.f);
        }
    }

    // final LN + head
    ln_k<<<MALL, 256>>>(x, lnfg, lnfb, xn);
    dim3 gHead(Vv / 64, MALL / 64, 1);
    gemm_k<false, false><<<gHead, 256>>>(xn, Cv, 0, 0, Whead, Vv, 0, 0,
                                         nullptr, nullptr,
                                         out, Vv, 0, 0, Cv, 1.f);
}

// round 2
// speedup vs baseline: 3.3492x; 3.3492x over previous
#include <cuda_runtime.h>
#include <math.h>

// Problem constants (fixed by setup_inputs)
#define Bv    8
#define Tv    512
#define Cv    512
#define Hv    8
#define DHv   64
#define Lv    2
#define Vv    512
#define FFv   2048
#define STEPS 4
#define MALL  (Bv*Tv)          // 4096 rows
#define SCALE 0.125f           // 1/sqrt(64)

// GEMM tile config
#define BM 128
#define BN 64
#define BK 32
#define ASTR (BK + 4)          // As row stride (36): banks m*4+k, conflict-free
#define BSTR (BN + 8)          // Bs row stride (72): banks k*8+n, conflict-free
#define SMEM_BYTES ((2*BM*ASTR + 2*BK*BSTR) * 4)   // 55296

// ---------------- scratch (device globals; no allocation) ----------------
__device__ float g_x [MALL*Cv];
__device__ float g_xn[MALL*Cv];
__device__ float g_q [MALL*Cv];
__device__ float g_k [MALL*Cv];
__device__ float g_v [MALL*Cv];
__device__ float g_y [MALL*Cv];
__device__ float g_att[Bv*Hv*Tv*Tv];
__device__ float g_h [MALL*FFv];

// ---------------- embedding ----------------
__global__ void embed_k(const int* __restrict__ idx,
                        const float* __restrict__ tok,
                        const float* __restrict__ pos,
                        float* __restrict__ x)
{
    int i = blockIdx.x * 256 + threadIdx.x;
    int c  = i & (Cv - 1);
    int bt = i >> 9;
    int t  = bt & (Tv - 1);
    x[i] = tok[idx[bt] * Cv + c] + pos[t * Cv + c];
}

// ---------------- layernorm ----------------
__device__ __forceinline__ float block_sum(float v, float* red)
{
    for (int o = 16; o > 0; o >>= 1) v += __shfl_xor_sync(0xffffffffu, v, o);
    int warp = threadIdx.x >> 5, lane = threadIdx.x & 31;
    if (lane == 0) red[warp] = v;
    __syncthreads();
    if (warp == 0) {
        float s = (lane < 8) ? red[lane] : 0.f;
        for (int o = 4; o > 0; o >>= 1) s += __shfl_xor_sync(0xffffffffu, s, o);
        if (lane == 0) red[0] = s;
    }
    __syncthreads();
    float r = red[0];
    __syncthreads();
    return r;
}

__global__ __launch_bounds__(256) void ln_k(const float* __restrict__ x,
                                            const float* __restrict__ g,
                                            const float* __restrict__ b,
                                            float* __restrict__ o)
{
    __shared__ float red[32];
    long row = blockIdx.x;
    const float* xr = x + row * Cv;
    int c0 = threadIdx.x, c1 = threadIdx.x + 256;
    float v0 = xr[c0], v1 = xr[c1];
    float mu = block_sum(v0 + v1, red) * (1.f / Cv);
    float d0 = v0 - mu, d1 = v1 - mu;
    float var = block_sum(d0 * d0 + d1 * d1, red) * (1.f / Cv);
    float inv = rsqrtf(var + 1e-5f);
    float* orow = o + row * Cv;
    orow[c0] = d0 * inv * g[c0] + b[c0];
    orow[c1] = d1 * inv * g[c1] + b[c1];
}

// ---------------- softmax over last dim (rows of 512) ----------------
__global__ __launch_bounds__(256) void softmax_k(float* __restrict__ a)
{
    __shared__ float red[32];
    long row = blockIdx.x;
    float* ar = a + row * Tv;
    int c0 = threadIdx.x, c1 = threadIdx.x + 256;
    float v0 = ar[c0], v1 = ar[c1];
    float m = fmaxf(v0, v1);
    for (int o = 16; o > 0; o >>= 1) m = fmaxf(m, __shfl_xor_sync(0xffffffffu, m, o));
    int warp = threadIdx.x >> 5, lane = threadIdx.x & 31;
    if (lane == 0) red[warp] = m;
    __syncthreads();
    if (warp == 0) {
        float s = (lane < 8) ? red[lane] : -1e30f;
        for (int o = 4; o > 0; o >>= 1) s = fmaxf(s, __shfl_xor_sync(0xffffffffu, s, o));
        if (lane == 0) red[0] = s;
    }
    __syncthreads();
    m = red[0];
    __syncthreads();
    float e0 = expf(v0 - m), e1 = expf(v1 - m);
    float s = block_sum(e0 + e1, red);
    float inv = 1.f / s;
    ar[c0] = e0 * inv;
    ar[c1] = e1 * inv;
}

// ---------------- tf32 tensor-core GEMM ----------------
__device__ __forceinline__ unsigned f2tf(float f)
{
    unsigned u;
    asm("cvt.rna.tf32.f32 %0, %1;" : "=r"(u) : "f"(f));
    return u;
}

// C[m,n] = act( scale * sum_k A[m,k] * B'[k,n] + bias[n] + res[m,n] )
// B'[k,n] = TRANSB ? B[n*ldb+k] : B[k*ldb+n]
// batch: z -> (z1=z>>3, z2=z&7)
// M % 128 == 0, N % 64 == 0, K % 32 == 0.
template <bool TRANSB, bool GELU_ACT>
__global__ __launch_bounds__(256) void gemm_tc(
    const float* __restrict__ A, int lda, long long sA1, long long sA2,
    const float* __restrict__ Bm, int ldb, long long sB1, long long sB2,
    const float* __restrict__ bias,
    const float* __restrict__ res,
    float* __restrict__ Cm, int ldc, long long sC1, long long sC2,
    int K, float scale)
{
    int z = blockIdx.z;
    int z1 = z >> 3, z2 = z & 7;
    A  += z1 * sA1 + z2 * sA2;
    Bm += z1 * sB1 + z2 * sB2;
    Cm += z1 * sC1 + z2 * sC2;

    extern __shared__ unsigned sm_[];
    unsigned* As = sm_;                         // [2][BM][ASTR]
    unsigned* Bs = sm_ + 2 * BM * ASTR;         // [2][BK][BSTR]
#define AS(b,m,k) As[(((b)*BM) + (m))*ASTR + (k)]
#define BS(b,k,n) Bs[(((b)*BK) + (k))*BSTR + (n)]

    const int tid  = threadIdx.x;
    const int lane = tid & 31;
    const int wid  = tid >> 5;
    const int mWarp = (wid >> 1) * 32;   // 4 m-warps
    const int nWarp = (wid & 1) * 32;    // 2 n-warps
    const int rowBase = blockIdx.y * BM;
    const int colBase = blockIdx.x * BN;

    const int r  = lane >> 2;   // 0..7
    const int cq = lane & 3;    // 0..3

    float acc[2][4][4];
#pragma unroll
    for (int mi = 0; mi < 2; mi++)
#pragma unroll
        for (int ni = 0; ni < 4; ni++)
#pragma unroll
            for (int t = 0; t < 4; t++) acc[mi][ni][t] = 0.f;

    const int KT = K / BK;

    float4 ra[4];   // A prefetch regs
    float4 rb[2];   // B prefetch regs

    // ---- load tile 0 ----
    {
        const int k0 = 0;
#pragma unroll
        for (int i = 0; i < 4; i++) {
            int f = tid + i * 256;
            int row = f >> 3, c4 = (f & 7) * 4;
            ra[i] = *(const float4*)(A + (long)(rowBase + row) * lda + k0 + c4);
        }
#pragma unroll
        for (int i = 0; i < 2; i++) {
            int f = tid + i * 256;
            if (TRANSB) {
                int n = f >> 3, k4 = (f & 7) * 4;
                rb[i] = *(const float4*)(Bm + (long)(colBase + n) * ldb + k0 + k4);
            } else {
                int kk = f >> 4, n4 = (f & 15) * 4;
                rb[i] = *(const float4*)(Bm + (long)(k0 + kk) * ldb + colBase + n4);
            }
        }
        // store to buf 0
#pragma unroll
        for (int i = 0; i < 4; i++) {
            int f = tid + i * 256;
            int row = f >> 3, c4 = (f & 7) * 4;
            AS(0, row, c4 + 0) = f2tf(ra[i].x);
            AS(0, row, c4 + 1) = f2tf(ra[i].y);
            AS(0, row, c4 + 2) = f2tf(ra[i].z);
            AS(0, row, c4 + 3) = f2tf(ra[i].w);
        }
#pragma unroll
        for (int i = 0; i < 2; i++) {
            int f = tid + i * 256;
            if (TRANSB) {
                int n = f >> 3, k4 = (f & 7) * 4;
                BS(0, k4 + 0, n) = f2tf(rb[i].x);
                BS(0, k4 + 1, n) = f2tf(rb[i].y);
                BS(0, k4 + 2, n) = f2tf(rb[i].z);
                BS(0, k4 + 3, n) = f2tf(rb[i].w);
            } else {
                int kk = f >> 4, n4 = (f & 15) * 4;
                BS(0, kk, n4 + 0) = f2tf(rb[i].x);
                BS(0, kk, n4 + 1) = f2tf(rb[i].y);
                BS(0, kk, n4 + 2) = f2tf(rb[i].z);
                BS(0, kk, n4 + 3) = f2tf(rb[i].w);
            }
        }
    }
    __syncthreads();

    for (int kt = 0; kt < KT; kt++) {
        const int buf = kt & 1;
        const bool hasNext = (kt + 1 < KT);

        if (hasNext) {
            const int k0 = (kt + 1) * BK;
#pragma unroll
            for (int i = 0; i < 4; i++) {
                int f = tid + i * 256;
                int row = f >> 3, c4 = (f & 7) * 4;
                ra[i] = *(const float4*)(A + (long)(rowBase + row) * lda + k0 + c4);
            }
#pragma unroll
            for (int i = 0; i < 2; i++) {
                int f = tid + i * 256;
                if (TRANSB) {
                    int n = f >> 3, k4 = (f & 7) * 4;
                    rb[i] = *(const float4*)(Bm + (long)(colBase + n) * ldb + k0 + k4);
                } else {
                    int kk = f >> 4, n4 = (f & 15) * 4;
                    rb[i] = *(const float4*)(Bm + (long)(k0 + kk) * ldb + colBase + n4);
                }
            }
        }

        // ---- compute on buf ----
#pragma unroll
        for (int ks = 0; ks < 4; ks++) {
            const int kb = ks * 8;
            unsigned a[2][4];
#pragma unroll
            for (int mi = 0; mi < 2; mi++) {
                int m = mWarp + mi * 16;
                a[mi][0] = AS(buf, m + r,     kb + cq);
                a[mi][1] = AS(buf, m + r + 8, kb + cq);
                a[mi][2] = AS(buf, m + r,     kb + cq + 4);
                a[mi][3] = AS(buf, m + r + 8, kb + cq + 4);
            }
            unsigned bb[4][2];
#pragma unroll
            for (int ni = 0; ni < 4; ni++) {
                int n = nWarp + ni * 8 + r;
                bb[ni][0] = BS(buf, kb + cq,     n);
                bb[ni][1] = BS(buf, kb + cq + 4, n);
            }
#pragma unroll
            for (int mi = 0; mi < 2; mi++)
#pragma unroll
                for (int ni = 0; ni < 4; ni++) {
                    asm volatile(
                        "mma.sync.aligned.m16n8k8.row.col.f32.tf32.tf32.f32 "
                        "{%0,%1,%2,%3}, {%4,%5,%6,%7}, {%8,%9}, {%0,%1,%2,%3};\n"
                        : "+f"(acc[mi][ni][0]), "+f"(acc[mi][ni][1]),
                          "+f"(acc[mi][ni][2]), "+f"(acc[mi][ni][3])
                        : "r"(a[mi][0]), "r"(a[mi][1]), "r"(a[mi][2]), "r"(a[mi][3]),
                          "r"(bb[ni][0]), "r"(bb[ni][1]));
                }
        }

        if (hasNext) {
            const int nb = buf ^ 1;
#pragma unroll
            for (int i = 0; i < 4; i++) {
                int f = tid + i * 256;
                int row = f >> 3, c4 = (f & 7) * 4;
                AS(nb, row, c4 + 0) = f2tf(ra[i].x);
                AS(nb, row, c4 + 1) = f2tf(ra[i].y);
                AS(nb, row, c4 + 2) = f2tf(ra[i].z);
                AS(nb, row, c4 + 3) = f2tf(ra[i].w);
            }
#pragma unroll
            for (int i = 0; i < 2; i++) {
                int f = tid + i * 256;
                if (TRANSB) {
                    int n = f >> 3, k4 = (f & 7) * 4;
                    BS(nb, k4 + 0, n) = f2tf(rb[i].x);
                    BS(nb, k4 + 1, n) = f2tf(rb[i].y);
                    BS(nb, k4 + 2, n) = f2tf(rb[i].z);
                    BS(nb, k4 + 3, n) = f2tf(rb[i].w);
                } else {
                    int kk = f >> 4, n4 = (f & 15) * 4;
                    BS(nb, kk, n4 + 0) = f2tf(rb[i].x);
                    BS(nb, kk, n4 + 1) = f2tf(rb[i].y);
                    BS(nb, kk, n4 + 2) = f2tf(rb[i].z);
                    BS(nb, kk, n4 + 3) = f2tf(rb[i].w);
                }
            }
        }
        __syncthreads();
    }

    // ---- epilogue ----
#pragma unroll
    for (int mi = 0; mi < 2; mi++) {
#pragma unroll
        for (int ni = 0; ni < 4; ni++) {
            int row0 = rowBase + mWarp + mi * 16 + r;
            int col  = colBase + nWarp + ni * 8 + 2 * cq;
#pragma unroll
            for (int half = 0; half < 2; half++) {
                int rr = row0 + half * 8;
                float v0 = acc[mi][ni][half * 2 + 0] * scale;
                float v1 = acc[mi][ni][half * 2 + 1] * scale;
                if (bias) { v0 += bias[col]; v1 += bias[col + 1]; }
                if (res) {
                    float2 rv = *(const float2*)(res + (long)rr * ldc + col);
                    v0 += rv.x; v1 += rv.y;
                }
                if (GELU_ACT) {
                    v0 = 0.5f * v0 * (1.f + erff(v0 * 0.70710678118654752f));
                    v1 = 0.5f * v1 * (1.f + erff(v1 * 0.70710678118654752f));
                }
                float2 ov; ov.x = v0; ov.y = v1;
                *(float2*)(Cm + (long)rr * ldc + col) = ov;
            }
        }
    }
#undef AS
#undef BS
}

// ---------------- host orchestration ----------------
extern "C" void kernel_launch(void* const* d_in, const int* in_sizes, int n_in,
                              void* d_out, int out_size)
{
    const int*   idx   = (const int*)  d_in[0];
    const float* tok   = (const float*)d_in[1];
    const float* pos   = (const float*)d_in[2];
    const float* ln1g  = (const float*)d_in[3];
    const float* ln1b  = (const float*)d_in[4];
    const float* Wq    = (const float*)d_in[5];
    const float* bq    = (const float*)d_in[6];
    const float* Wk    = (const float*)d_in[7];
    const float* bk    = (const float*)d_in[8];
    const float* Wv    = (const float*)d_in[9];
    const float* bv    = (const float*)d_in[10];
    const float* Wp    = (const float*)d_in[11];
    const float* bp    = (const float*)d_in[12];
    const float* ln2g  = (const float*)d_in[13];
    const float* ln2b  = (const float*)d_in[14];
    const float* W1    = (const float*)d_in[15];
    const float* b1    = (const float*)d_in[16];
    const float* W2    = (const float*)d_in[17];
    const float* b2    = (const float*)d_in[18];
    const float* lnfg  = (const float*)d_in[19];
    const float* lnfb  = (const float*)d_in[20];
    const float* Whead = (const float*)d_in[21];
    float* out = (float*)d_out;

    float *x, *xn, *q, *k, *v, *y, *att, *h;
    cudaGetSymbolAddress((void**)&x,   g_x);
    cudaGetSymbolAddress((void**)&xn,  g_xn);
    cudaGetSymbolAddress((void**)&q,   g_q);
    cudaGetSymbolAddress((void**)&k,   g_k);
    cudaGetSymbolAddress((void**)&v,   g_v);
    cudaGetSymbolAddress((void**)&y,   g_y);
    cudaGetSymbolAddress((void**)&att, g_att);
    cudaGetSymbolAddress((void**)&h,   g_h);

    cudaFuncSetAttribute(gemm_tc<false, false>,
                         cudaFuncAttributeMaxDynamicSharedMemorySize, SMEM_BYTES);
    cudaFuncSetAttribute(gemm_tc<true,  false>,
                         cudaFuncAttributeMaxDynamicSharedMemorySize, SMEM_BYTES);
    cudaFuncSetAttribute(gemm_tc<false, true >,
                         cudaFuncAttributeMaxDynamicSharedMemorySize, SMEM_BYTES);

    const long long sTC  = (long long)Tv * Cv;
    const long long sHTT = (long long)Hv * Tv * Tv;
    const long long sTT  = (long long)Tv * Tv;

    embed_k<<<(MALL * Cv) / 256, 256>>>(idx, tok, pos, x);

    for (int s = 0; s < STEPS; s++) {
        for (int l = 0; l < Lv; l++) {
            const float* wq = Wq + (long)l * Cv * Cv;
            const float* wk = Wk + (long)l * Cv * Cv;
            const float* wv = Wv + (long)l * Cv * Cv;
            const float* wp = Wp + (long)l * Cv * Cv;
            const float* w1 = W1 + (long)l * Cv * FFv;
            const float* w2 = W2 + (long)l * FFv * Cv;

            ln_k<<<MALL, 256>>>(x, ln1g + l * Cv, ln1b + l * Cv, xn);

            dim3 gProj(Cv / BN, MALL / BM, 1);
            gemm_tc<false, false><<<gProj, 256, SMEM_BYTES>>>(
                xn, Cv, 0, 0, wq, Cv, 0, 0, bq + l * Cv, nullptr,
                q, Cv, 0, 0, Cv, 1.f);
            gemm_tc<false, false><<<gProj, 256, SMEM_BYTES>>>(
                xn, Cv, 0, 0, wk, Cv, 0, 0, bk + l * Cv, nullptr,
                k, Cv, 0, 0, Cv, 1.f);
            gemm_tc<false, false><<<gProj, 256, SMEM_BYTES>>>(
                xn, Cv, 0, 0, wv, Cv, 0, 0, bv + l * Cv, nullptr,
                v, Cv, 0, 0, Cv, 1.f);

            // att = SCALE * q @ k^T  (batched over b,h)
            dim3 gQK(Tv / BN, Tv / BM, Bv * Hv);
            gemm_tc<true, false><<<gQK, 256, SMEM_BYTES>>>(
                q, Cv, sTC, DHv, k, Cv, sTC, DHv, nullptr, nullptr,
                att, Tv, sHTT, sTT, DHv, SCALE);

            softmax_k<<<Bv * Hv * Tv, 256>>>(att);

            // y = att @ v
            dim3 gAV(DHv / BN, Tv / BM, Bv * Hv);
            gemm_tc<false, false><<<gAV, 256, SMEM_BYTES>>>(
                att, Tv, sHTT, sTT, v, Cv, sTC, DHv, nullptr, nullptr,
                y, Cv, sTC, DHv, Tv, 1.f);

            // x = x + y @ Wp + bp
            gemm_tc<false, false><<<gProj, 256, SMEM_BYTES>>>(
                y, Cv, 0, 0, wp, Cv, 0, 0, bp + l * Cv, x,
                x, Cv, 0, 0, Cv, 1.f);

            ln_k<<<MALL, 256>>>(x, ln2g + l * Cv, ln2b + l * Cv, xn);

            // h = gelu(xn @ W1 + b1)
            dim3 gFF1(FFv / BN, MALL / BM, 1);
            gemm_tc<false, true><<<gFF1, 256, SMEM_BYTES>>>(
                xn, Cv, 0, 0, w1, FFv, 0, 0, b1 + l * FFv, nullptr,
                h, FFv, 0, 0, Cv, 1.f);

            // x = x + h @ W2 + b2
            gemm_tc<false, false><<<gProj, 256, SMEM_BYTES>>>(
                h, FFv, 0, 0, w2, Cv, 0, 0, b2 + l * Cv, x,
                x, Cv, 0, 0, FFv, 1.f);
        }
    }

    ln_k<<<MALL, 256>>>(x, lnfg, lnfb, xn);
    dim3 gHead(Vv / BN, MALL / BM, 1);
    gemm_tc<false, false><<<gHead, 256, SMEM_BYTES>>>(
        xn, Cv, 0, 0, Whead, Vv, 0, 0, nullptr, nullptr,
        out, Vv, 0, 0, Cv, 1.f);
}